// round 2
// baseline (speedup 1.0000x reference)
#include <cuda_runtime.h>
#include <math.h>
#include <float.h>

#define ND 2048
#define NS 1024
#define DIN 768
#define DOUT 64

#define LOG2E 1.4426950408889634f
#define LN2   0.6931471805599453f
#define LOGA  (-7.6246189861593985f)   /* -ln(2048) */
#define LOGB  (-6.9314718055994531f)   /* -ln(1024) */
#define BLUR2 0.0025f

// ---- static device scratch (no cudaMalloc allowed) ----
__device__ float g_x[ND * DOUT];
__device__ float g_y[NS * DOUT];
__device__ float g_Cxy[ND * NS];
__device__ float g_Cyx[NS * ND];
__device__ float g_Cxx[ND * ND];
__device__ float g_Cyy[NS * NS];
__device__ float g_f_ab[2][ND];
__device__ float g_g_ab[2][NS];
__device__ float g_f_aa[2][ND];
__device__ float g_g_bb[2][NS];
__device__ float g_eps[21];

// ---------------------------------------------------------------------------
// zero the parity-0 potential buffers (read by the init step)
// ---------------------------------------------------------------------------
__global__ void zero_kernel() {
    int t = threadIdx.x + blockIdx.x * blockDim.x;
    if (t < ND) { g_f_ab[0][t] = 0.f; g_f_aa[0][t] = 0.f; }
    if (t < NS) { g_g_ab[0][t] = 0.f; g_g_bb[0][t] = 0.f; }
}

// ---------------------------------------------------------------------------
// projection: x = d @ M  (2048x768 * 768x64), y = s @ M (1024x768 * 768x64)
// 64-row tiles, K-tiles of 32, 4x4 register blocking per thread.
// ---------------------------------------------------------------------------
__global__ __launch_bounds__(256) void proj_kernel(const float* __restrict__ d,
                                                   const float* __restrict__ s,
                                                   const float* __restrict__ M) {
    __shared__ float ds[64][33];   // [row][k], padded
    __shared__ float Ms[32][64];   // [k][col]

    int b = blockIdx.x;
    const float* src;
    float* dst;
    int rowbase;
    if (b < 32) { src = d; dst = g_x; rowbase = b * 64; }
    else        { src = s; dst = g_y; rowbase = (b - 32) * 64; }

    int tid = threadIdx.x;
    int tr = tid >> 4, tc = tid & 15;
    float acc[4][4];
#pragma unroll
    for (int i = 0; i < 4; i++)
#pragma unroll
        for (int j = 0; j < 4; j++) acc[i][j] = 0.f;

    for (int kt = 0; kt < DIN; kt += 32) {
        __syncthreads();
        for (int i = tid; i < 64 * 32; i += 256) {
            int rr = i >> 5, kk = i & 31;
            ds[rr][kk] = src[(size_t)(rowbase + rr) * DIN + kt + kk];
        }
        for (int i = tid; i < 32 * 64; i += 256) {
            int kr = i >> 6, kc = i & 63;
            Ms[kr][kc] = M[(size_t)(kt + kr) * 64 + kc];
        }
        __syncthreads();
#pragma unroll
        for (int kk = 0; kk < 32; kk++) {
            float4 bv = *reinterpret_cast<const float4*>(&Ms[kk][tc * 4]);
#pragma unroll
            for (int i = 0; i < 4; i++) {
                float a = ds[tr * 4 + i][kk];
                acc[i][0] = fmaf(a, bv.x, acc[i][0]);
                acc[i][1] = fmaf(a, bv.y, acc[i][1]);
                acc[i][2] = fmaf(a, bv.z, acc[i][2]);
                acc[i][3] = fmaf(a, bv.w, acc[i][3]);
            }
        }
    }
#pragma unroll
    for (int i = 0; i < 4; i++) {
        float4 v = make_float4(acc[i][0], acc[i][1], acc[i][2], acc[i][3]);
        *reinterpret_cast<float4*>(&dst[(size_t)(rowbase + tr * 4 + i) * 64 + tc * 4]) = v;
    }
}

// ---------------------------------------------------------------------------
// diameter + eps schedule: per-dim min/max over union of x and y,
// diam^2 = sum (max-min)^2 ; eps_t = max(diam2 * 0.25^t, blur^2)
// ---------------------------------------------------------------------------
__global__ __launch_bounds__(512) void minmax_eps_kernel() {
    __shared__ float smn[512], smx[512];
    int tid = threadIdx.x;
    int dim = tid & 63;
    int grp = tid >> 6;   // 0..7
    float mn = FLT_MAX, mx = -FLT_MAX;
    for (int r = grp; r < ND; r += 8) {
        float v = g_x[r * 64 + dim];
        mn = fminf(mn, v); mx = fmaxf(mx, v);
    }
    for (int r = grp; r < NS; r += 8) {
        float v = g_y[r * 64 + dim];
        mn = fminf(mn, v); mx = fmaxf(mx, v);
    }
    smn[tid] = mn; smx[tid] = mx;
    __syncthreads();
    if (grp == 0) {
        for (int gq = 1; gq < 8; gq++) {
            mn = fminf(mn, smn[gq * 64 + dim]);
            mx = fmaxf(mx, smx[gq * 64 + dim]);
        }
        float dd = mx - mn;
        smn[dim] = dd * dd;
    }
    __syncthreads();
    if (tid == 0) {
        float diam2 = 0.f;
        for (int k = 0; k < 64; k++) diam2 += smn[k];
        float e = diam2;
        for (int t = 0; t < 20; t++) {
            g_eps[t] = fmaxf(e, BLUR2);
            e *= 0.25f;
        }
        g_eps[20] = BLUR2;
    }
}

// ---------------------------------------------------------------------------
// cost matrices: C[i][j] = 0.5*|a_i|^2 + 0.5*|b_j|^2 - a_i . b_j
// one kernel covers Cxy / Cyx / Cxx / Cyy via block index ranges.
// 64x64 output tiles, K = 64 (full), 4x4 register blocking.
// ---------------------------------------------------------------------------
__global__ __launch_bounds__(256) void cost_kernel() {
    int b = blockIdx.x;
    const float *A, *B;
    float* C;
    int NB, bi, bj;
    if (b < 512)       { A = g_x; B = g_y; C = g_Cxy; NB = NS; int i = b;        bi = i >> 4; bj = i & 15; }
    else if (b < 1024) { A = g_y; B = g_x; C = g_Cyx; NB = ND; int i = b - 512;  bi = i >> 5; bj = i & 31; }
    else if (b < 2048) { A = g_x; B = g_x; C = g_Cxx; NB = ND; int i = b - 1024; bi = i >> 5; bj = i & 31; }
    else               { A = g_y; B = g_y; C = g_Cyy; NB = NS; int i = b - 2048; bi = i >> 4; bj = i & 15; }

    __shared__ float As[64][65];    // [row][k]
    __shared__ float BsT[64][68];   // [k][col]
    __shared__ float an[64], bn[64];

    int tid = threadIdx.x;
    for (int i = tid; i < 64 * 16; i += 256) {
        int rr = i >> 4, kq = i & 15;
        float4 v = *reinterpret_cast<const float4*>(&A[(size_t)(bi * 64 + rr) * 64 + kq * 4]);
        As[rr][kq * 4 + 0] = v.x; As[rr][kq * 4 + 1] = v.y;
        As[rr][kq * 4 + 2] = v.z; As[rr][kq * 4 + 3] = v.w;
    }
    for (int i = tid; i < 64 * 16; i += 256) {
        int rr = i >> 4, kq = i & 15;
        float4 v = *reinterpret_cast<const float4*>(&B[(size_t)(bj * 64 + rr) * 64 + kq * 4]);
        BsT[kq * 4 + 0][rr] = v.x; BsT[kq * 4 + 1][rr] = v.y;
        BsT[kq * 4 + 2][rr] = v.z; BsT[kq * 4 + 3][rr] = v.w;
    }
    __syncthreads();
    if (tid < 64) {
        float sacc = 0.f;
#pragma unroll
        for (int k = 0; k < 64; k++) sacc = fmaf(As[tid][k], As[tid][k], sacc);
        an[tid] = 0.5f * sacc;
    } else if (tid < 128) {
        int c = tid - 64;
        float sacc = 0.f;
#pragma unroll
        for (int k = 0; k < 64; k++) sacc = fmaf(BsT[k][c], BsT[k][c], sacc);
        bn[c] = 0.5f * sacc;
    }
    __syncthreads();

    int tr = tid >> 4, tc = tid & 15;
    float acc[4][4];
#pragma unroll
    for (int i = 0; i < 4; i++)
#pragma unroll
        for (int j = 0; j < 4; j++) acc[i][j] = 0.f;

#pragma unroll
    for (int kk = 0; kk < 64; kk++) {
        float4 bv = *reinterpret_cast<const float4*>(&BsT[kk][tc * 4]);
#pragma unroll
        for (int i = 0; i < 4; i++) {
            float a = As[tr * 4 + i][kk];
            acc[i][0] = fmaf(a, bv.x, acc[i][0]);
            acc[i][1] = fmaf(a, bv.y, acc[i][1]);
            acc[i][2] = fmaf(a, bv.z, acc[i][2]);
            acc[i][3] = fmaf(a, bv.w, acc[i][3]);
        }
    }
#pragma unroll
    for (int i = 0; i < 4; i++) {
        int row = bi * 64 + tr * 4 + i;
        float4 o;
        o.x = an[tr * 4 + i] + bn[tc * 4 + 0] - acc[i][0];
        o.y = an[tr * 4 + i] + bn[tc * 4 + 1] - acc[i][1];
        o.z = an[tr * 4 + i] + bn[tc * 4 + 2] - acc[i][2];
        o.w = an[tr * 4 + i] + bn[tc * 4 + 3] - acc[i][3];
        *reinterpret_cast<float4*>(&C[(size_t)row * NB + bj * 64 + tc * 4]) = o;
    }
}

// ---------------------------------------------------------------------------
// one Sinkhorn sweep: 4 tasks (ft / gt / f_aa / g_bb), one warp per row.
// ft_i = -eps*(logw + ln2*LSE2_j((g_j - C_ij) * log2e/eps))
// out  = blend ? 0.5*(old + ft) : ft
// ---------------------------------------------------------------------------
__global__ __launch_bounds__(256) void step_kernel(int step, int rp, int wp,
                                                   float blend, int mask) {
    int task = blockIdx.y;
    if (!((mask >> task) & 1)) return;

    const float* C;
    const float* gv;
    const float* oldv;
    float* outv;
    int len, nrows;
    float logw;
    switch (task) {
        case 0: C = g_Cxy; len = NS; nrows = ND; gv = g_g_ab[rp]; oldv = g_f_ab[rp]; outv = g_f_ab[wp]; logw = LOGB; break;
        case 1: C = g_Cyx; len = ND; nrows = NS; gv = g_f_ab[rp]; oldv = g_g_ab[rp]; outv = g_g_ab[wp]; logw = LOGA; break;
        case 2: C = g_Cxx; len = ND; nrows = ND; gv = g_f_aa[rp]; oldv = g_f_aa[rp]; outv = g_f_aa[wp]; logw = LOGA; break;
        default:C = g_Cyy; len = NS; nrows = NS; gv = g_g_bb[rp]; oldv = g_g_bb[rp]; outv = g_g_bb[wp]; logw = LOGB; break;
    }

    float eps = g_eps[step];
    float ie = LOG2E / eps;

    __shared__ float gs[2048];
    int tid = threadIdx.x;
    for (int j = tid; j < len; j += 256) gs[j] = gv[j] * ie;
    __syncthreads();

    int wid = tid >> 5, lane = tid & 31;
    int row = blockIdx.x * 8 + wid;
    if (row >= nrows) return;

    const float* Crow = C + (size_t)row * len;
    float m = 0.f, ssum = 0.f;

    for (int base = 0; base < len; base += 1024) {
        float u[32];
#pragma unroll
        for (int k = 0; k < 32; k++) {
            int j = base + lane + (k << 5);
            u[k] = fmaf(Crow[j], -ie, gs[j]);
        }
        float mloc = u[0];
#pragma unroll
        for (int k = 1; k < 32; k++) mloc = fmaxf(mloc, u[k]);
        float sl = 0.f;
#pragma unroll
        for (int k = 0; k < 32; k++) sl += exp2f(u[k] - mloc);
        if (base == 0) {
            m = mloc; ssum = sl;
        } else {
            float Mx = fmaxf(m, mloc);
            ssum = ssum * exp2f(m - Mx) + sl * exp2f(mloc - Mx);
            m = Mx;
        }
    }
#pragma unroll
    for (int off = 16; off > 0; off >>= 1) {
        float m2 = __shfl_xor_sync(0xffffffffu, m, off);
        float s2 = __shfl_xor_sync(0xffffffffu, ssum, off);
        float Mx = fmaxf(m, m2);
        ssum = ssum * exp2f(m - Mx) + s2 * exp2f(m2 - Mx);
        m = Mx;
    }
    if (lane == 0) {
        float ft = -eps * (logw + LN2 * (m + __log2f(ssum)));
        outv[row] = (blend != 0.f) ? 0.5f * (oldv[row] + ft) : ft;
    }
}

// ---------------------------------------------------------------------------
// final scalar: loss = mean(f_ab - f_aa) + mean(g_ab - g_bb); out = exp(-loss)
// ---------------------------------------------------------------------------
__global__ __launch_bounds__(256) void reduce_kernel(float* out) {
    __shared__ double sh[256];
    int tid = threadIdx.x;
    double a1 = 0.0, a2 = 0.0;
    for (int i = tid; i < ND; i += 256)
        a1 += (double)g_f_ab[0][i] - (double)g_f_aa[0][i];
    for (int i = tid; i < NS; i += 256)
        a2 += (double)g_g_ab[0][i] - (double)g_g_bb[0][i];
    sh[tid] = a1 / (double)ND + a2 / (double)NS;
    __syncthreads();
    for (int off = 128; off > 0; off >>= 1) {
        if (tid < off) sh[tid] += sh[tid + off];
        __syncthreads();
    }
    if (tid == 0) out[0] = expf((float)(-sh[0]));
}

// ---------------------------------------------------------------------------
extern "C" void kernel_launch(void* const* d_in, const int* in_sizes, int n_in,
                              void* d_out, int out_size) {
    const float* d = (const float*)d_in[0];   // [2048, 768]
    const float* s = (const float*)d_in[1];   // [1024, 768]
    const float* M = (const float*)d_in[2];   // [768, 64]
    float* out = (float*)d_out;

    zero_kernel<<<2, 1024>>>();
    proj_kernel<<<48, 256>>>(d, s, M);
    minmax_eps_kernel<<<1, 512>>>();
    cost_kernel<<<2304, 256>>>();

    dim3 sgrid(256, 4);
    // init: reads parity 0 (zeros), writes parity 1, eps = eps_list[0]
    step_kernel<<<sgrid, 256>>>(0, 0, 1, 0.f, 0xF);
    // 20 scan steps with 0.5 averaging
    for (int t = 0; t < 20; t++) {
        int rp = 1 - (t & 1);
        int wp = t & 1;
        step_kernel<<<sgrid, 256>>>(t, rp, wp, 0.5f, 0xF);
    }
    // final extrapolation at eps = blur^2 (index 20), no averaging.
    // first f_ab, f_aa, g_bb (read parity 1 -> write parity 0)
    step_kernel<<<sgrid, 256>>>(20, 1, 0, 0.f, 0b1101);
    // then g_ab from the NEW f_ab (read parity 0 -> write parity 0)
    step_kernel<<<sgrid, 256>>>(20, 0, 0, 0.f, 0b0010);

    reduce_kernel<<<1, 256>>>(out);
}

// round 3
// speedup vs baseline: 1.0059x; 1.0059x over previous
#include <cuda_runtime.h>
#include <math.h>
#include <float.h>

#define ND 2048
#define NS 1024
#define DIN 768
#define DOUT 64

#define LOG2E 1.4426950408889634f
#define LN2   0.6931471805599453f
#define LOGA  (-7.6246189861593985f)   /* -ln(2048) */
#define LOGB  (-6.9314718055994531f)   /* -ln(1024) */
#define BLUR2 0.0025f

// ---- static device scratch (no cudaMalloc allowed) ----
__device__ float g_x[ND * DOUT];
__device__ float g_y[NS * DOUT];
__device__ float g_Cxy[ND * NS];
__device__ float g_Cyx[NS * ND];
__device__ float g_Cxx[ND * ND];
__device__ float g_Cyy[NS * NS];
__device__ float g_f_ab[2][ND];
__device__ float g_g_ab[2][NS];
__device__ float g_f_aa[2][ND];
__device__ float g_g_bb[2][NS];
__device__ float g_eps[21];

// ---------------------------------------------------------------------------
// zero the parity-0 potential buffers (read by the init step)
// ---------------------------------------------------------------------------
__global__ void zero_kernel() {
    int t = threadIdx.x + blockIdx.x * blockDim.x;
    if (t < ND) { g_f_ab[0][t] = 0.f; g_f_aa[0][t] = 0.f; }
    if (t < NS) { g_g_ab[0][t] = 0.f; g_g_bb[0][t] = 0.f; }
}

// ---------------------------------------------------------------------------
// projection: x = d @ M  (2048x768 * 768x64), y = s @ M (1024x768 * 768x64)
// 64-row tiles, K-tiles of 32, 4x4 register blocking per thread.
// ---------------------------------------------------------------------------
__global__ __launch_bounds__(256) void proj_kernel(const float* __restrict__ d,
                                                   const float* __restrict__ s,
                                                   const float* __restrict__ M) {
    __shared__ float ds[64][33];   // [row][k], padded
    __shared__ float Ms[32][64];   // [k][col]

    int b = blockIdx.x;
    const float* src;
    float* dst;
    int rowbase;
    if (b < 32) { src = d; dst = g_x; rowbase = b * 64; }
    else        { src = s; dst = g_y; rowbase = (b - 32) * 64; }

    int tid = threadIdx.x;
    int tr = tid >> 4, tc = tid & 15;
    float acc[4][4];
#pragma unroll
    for (int i = 0; i < 4; i++)
#pragma unroll
        for (int j = 0; j < 4; j++) acc[i][j] = 0.f;

    for (int kt = 0; kt < DIN; kt += 32) {
        __syncthreads();
        for (int i = tid; i < 64 * 32; i += 256) {
            int rr = i >> 5, kk = i & 31;
            ds[rr][kk] = src[(size_t)(rowbase + rr) * DIN + kt + kk];
        }
        for (int i = tid; i < 32 * 64; i += 256) {
            int kr = i >> 6, kc = i & 63;
            Ms[kr][kc] = M[(size_t)(kt + kr) * 64 + kc];
        }
        __syncthreads();
#pragma unroll
        for (int kk = 0; kk < 32; kk++) {
            float4 bv = *reinterpret_cast<const float4*>(&Ms[kk][tc * 4]);
#pragma unroll
            for (int i = 0; i < 4; i++) {
                float a = ds[tr * 4 + i][kk];
                acc[i][0] = fmaf(a, bv.x, acc[i][0]);
                acc[i][1] = fmaf(a, bv.y, acc[i][1]);
                acc[i][2] = fmaf(a, bv.z, acc[i][2]);
                acc[i][3] = fmaf(a, bv.w, acc[i][3]);
            }
        }
    }
#pragma unroll
    for (int i = 0; i < 4; i++) {
        float4 v = make_float4(acc[i][0], acc[i][1], acc[i][2], acc[i][3]);
        *reinterpret_cast<float4*>(&dst[(size_t)(rowbase + tr * 4 + i) * 64 + tc * 4]) = v;
    }
}

// ---------------------------------------------------------------------------
// diameter + eps schedule: per-dim min/max over union of x and y,
// diam^2 = sum (max-min)^2 ; eps_t = max(diam2 * 0.25^t, blur^2)
// ---------------------------------------------------------------------------
__global__ __launch_bounds__(512) void minmax_eps_kernel() {
    __shared__ float smn[512], smx[512];
    int tid = threadIdx.x;
    int dim = tid & 63;
    int grp = tid >> 6;   // 0..7
    float mn = FLT_MAX, mx = -FLT_MAX;
    for (int r = grp; r < ND; r += 8) {
        float v = g_x[r * 64 + dim];
        mn = fminf(mn, v); mx = fmaxf(mx, v);
    }
    for (int r = grp; r < NS; r += 8) {
        float v = g_y[r * 64 + dim];
        mn = fminf(mn, v); mx = fmaxf(mx, v);
    }
    smn[tid] = mn; smx[tid] = mx;
    __syncthreads();
    if (grp == 0) {
        for (int gq = 1; gq < 8; gq++) {
            mn = fminf(mn, smn[gq * 64 + dim]);
            mx = fmaxf(mx, smx[gq * 64 + dim]);
        }
        float dd = mx - mn;
        smn[dim] = dd * dd;
    }
    __syncthreads();
    if (tid == 0) {
        float diam2 = 0.f;
        for (int k = 0; k < 64; k++) diam2 += smn[k];
        float e = diam2;
        for (int t = 0; t < 20; t++) {
            g_eps[t] = fmaxf(e, BLUR2);
            e *= 0.25f;
        }
        g_eps[20] = BLUR2;
    }
}

// ---------------------------------------------------------------------------
// cost matrices: C[i][j] = 0.5*|a_i|^2 + 0.5*|b_j|^2 - a_i . b_j
// one kernel covers Cxy / Cyx / Cxx / Cyy via block index ranges.
// 64x64 output tiles, K = 64 (full), 4x4 register blocking.
// ---------------------------------------------------------------------------
__global__ __launch_bounds__(256) void cost_kernel() {
    int b = blockIdx.x;
    const float *A, *B;
    float* C;
    int NB, bi, bj;
    if (b < 512)       { A = g_x; B = g_y; C = g_Cxy; NB = NS; int i = b;        bi = i >> 4; bj = i & 15; }
    else if (b < 1024) { A = g_y; B = g_x; C = g_Cyx; NB = ND; int i = b - 512;  bi = i >> 5; bj = i & 31; }
    else if (b < 2048) { A = g_x; B = g_x; C = g_Cxx; NB = ND; int i = b - 1024; bi = i >> 5; bj = i & 31; }
    else               { A = g_y; B = g_y; C = g_Cyy; NB = NS; int i = b - 2048; bi = i >> 4; bj = i & 15; }

    __shared__ float As[64][65];    // [row][k]
    __shared__ float BsT[64][68];   // [k][col]
    __shared__ float an[64], bn[64];

    int tid = threadIdx.x;
    for (int i = tid; i < 64 * 16; i += 256) {
        int rr = i >> 4, kq = i & 15;
        float4 v = *reinterpret_cast<const float4*>(&A[(size_t)(bi * 64 + rr) * 64 + kq * 4]);
        As[rr][kq * 4 + 0] = v.x; As[rr][kq * 4 + 1] = v.y;
        As[rr][kq * 4 + 2] = v.z; As[rr][kq * 4 + 3] = v.w;
    }
    for (int i = tid; i < 64 * 16; i += 256) {
        int rr = i >> 4, kq = i & 15;
        float4 v = *reinterpret_cast<const float4*>(&B[(size_t)(bj * 64 + rr) * 64 + kq * 4]);
        BsT[kq * 4 + 0][rr] = v.x; BsT[kq * 4 + 1][rr] = v.y;
        BsT[kq * 4 + 2][rr] = v.z; BsT[kq * 4 + 3][rr] = v.w;
    }
    __syncthreads();
    if (tid < 64) {
        float sacc = 0.f;
#pragma unroll
        for (int k = 0; k < 64; k++) sacc = fmaf(As[tid][k], As[tid][k], sacc);
        an[tid] = 0.5f * sacc;
    } else if (tid < 128) {
        int c = tid - 64;
        float sacc = 0.f;
#pragma unroll
        for (int k = 0; k < 64; k++) sacc = fmaf(BsT[k][c], BsT[k][c], sacc);
        bn[c] = 0.5f * sacc;
    }
    __syncthreads();

    int tr = tid >> 4, tc = tid & 15;
    float acc[4][4];
#pragma unroll
    for (int i = 0; i < 4; i++)
#pragma unroll
        for (int j = 0; j < 4; j++) acc[i][j] = 0.f;

#pragma unroll
    for (int kk = 0; kk < 64; kk++) {
        float4 bv = *reinterpret_cast<const float4*>(&BsT[kk][tc * 4]);
#pragma unroll
        for (int i = 0; i < 4; i++) {
            float a = As[tr * 4 + i][kk];
            acc[i][0] = fmaf(a, bv.x, acc[i][0]);
            acc[i][1] = fmaf(a, bv.y, acc[i][1]);
            acc[i][2] = fmaf(a, bv.z, acc[i][2]);
            acc[i][3] = fmaf(a, bv.w, acc[i][3]);
        }
    }
#pragma unroll
    for (int i = 0; i < 4; i++) {
        int row = bi * 64 + tr * 4 + i;
        float4 o;
        o.x = an[tr * 4 + i] + bn[tc * 4 + 0] - acc[i][0];
        o.y = an[tr * 4 + i] + bn[tc * 4 + 1] - acc[i][1];
        o.z = an[tr * 4 + i] + bn[tc * 4 + 2] - acc[i][2];
        o.w = an[tr * 4 + i] + bn[tc * 4 + 3] - acc[i][3];
        *reinterpret_cast<float4*>(&C[(size_t)row * NB + bj * 64 + tc * 4]) = o;
    }
}

// ---------------------------------------------------------------------------
// one Sinkhorn sweep: 4 tasks (ft / gt / f_aa / g_bb), one warp per row.
// ft_i = -eps*(logw + ln2*LSE2_j((g_j - C_ij) * log2e/eps))
// out  = blend ? 0.5*(old + ft) : ft
// ---------------------------------------------------------------------------
__global__ __launch_bounds__(256) void step_kernel(int step, int rp, int wp,
                                                   float blend, int mask) {
    int task = blockIdx.y;
    if (!((mask >> task) & 1)) return;

    const float* C;
    const float* gv;
    const float* oldv;
    float* outv;
    int len, nrows;
    float logw;
    switch (task) {
        case 0: C = g_Cxy; len = NS; nrows = ND; gv = g_g_ab[rp]; oldv = g_f_ab[rp]; outv = g_f_ab[wp]; logw = LOGB; break;
        case 1: C = g_Cyx; len = ND; nrows = NS; gv = g_f_ab[rp]; oldv = g_g_ab[rp]; outv = g_g_ab[wp]; logw = LOGA; break;
        case 2: C = g_Cxx; len = ND; nrows = ND; gv = g_f_aa[rp]; oldv = g_f_aa[rp]; outv = g_f_aa[wp]; logw = LOGA; break;
        default:C = g_Cyy; len = NS; nrows = NS; gv = g_g_bb[rp]; oldv = g_g_bb[rp]; outv = g_g_bb[wp]; logw = LOGB; break;
    }

    float eps = g_eps[step];
    float ie = LOG2E / eps;

    __shared__ float gs[2048];
    int tid = threadIdx.x;
    for (int j = tid; j < len; j += 256) gs[j] = gv[j] * ie;
    __syncthreads();

    int wid = tid >> 5, lane = tid & 31;
    int row = blockIdx.x * 8 + wid;
    if (row >= nrows) return;

    const float* Crow = C + (size_t)row * len;
    float m = 0.f, ssum = 0.f;

    for (int base = 0; base < len; base += 1024) {
        float u[32];
#pragma unroll
        for (int k = 0; k < 32; k++) {
            int j = base + lane + (k << 5);
            u[k] = fmaf(Crow[j], -ie, gs[j]);
        }
        float mloc = u[0];
#pragma unroll
        for (int k = 1; k < 32; k++) mloc = fmaxf(mloc, u[k]);
        float sl = 0.f;
#pragma unroll
        for (int k = 0; k < 32; k++) sl += exp2f(u[k] - mloc);
        if (base == 0) {
            m = mloc; ssum = sl;
        } else {
            float Mx = fmaxf(m, mloc);
            ssum = ssum * exp2f(m - Mx) + sl * exp2f(mloc - Mx);
            m = Mx;
        }
    }
#pragma unroll
    for (int off = 16; off > 0; off >>= 1) {
        float m2 = __shfl_xor_sync(0xffffffffu, m, off);
        float s2 = __shfl_xor_sync(0xffffffffu, ssum, off);
        float Mx = fmaxf(m, m2);
        ssum = ssum * exp2f(m - Mx) + s2 * exp2f(m2 - Mx);
        m = Mx;
    }
    if (lane == 0) {
        float ft = -eps * (logw + LN2 * (m + __log2f(ssum)));
        outv[row] = (blend != 0.f) ? 0.5f * (oldv[row] + ft) : ft;
    }
}

// ---------------------------------------------------------------------------
// final scalar: loss = mean(f_ab - f_aa) + mean(g_ab - g_bb); out = exp(-loss)
// ---------------------------------------------------------------------------
__global__ __launch_bounds__(256) void reduce_kernel(float* out) {
    __shared__ double sh[256];
    int tid = threadIdx.x;
    double a1 = 0.0, a2 = 0.0;
    for (int i = tid; i < ND; i += 256)
        a1 += (double)g_f_ab[0][i] - (double)g_f_aa[0][i];
    for (int i = tid; i < NS; i += 256)
        a2 += (double)g_g_ab[0][i] - (double)g_g_bb[0][i];
    sh[tid] = a1 / (double)ND + a2 / (double)NS;
    __syncthreads();
    for (int off = 128; off > 0; off >>= 1) {
        if (tid < off) sh[tid] += sh[tid + off];
        __syncthreads();
    }
    if (tid == 0) out[0] = expf((float)(-sh[0]));
}

// ---------------------------------------------------------------------------
extern "C" void kernel_launch(void* const* d_in, const int* in_sizes, int n_in,
                              void* d_out, int out_size) {
    const float* d = (const float*)d_in[0];   // [2048, 768]
    const float* s = (const float*)d_in[1];   // [1024, 768]
    const float* M = (const float*)d_in[2];   // [768, 64]
    float* out = (float*)d_out;

    zero_kernel<<<2, 1024>>>();
    proj_kernel<<<48, 256>>>(d, s, M);
    minmax_eps_kernel<<<1, 512>>>();
    cost_kernel<<<2304, 256>>>();

    dim3 sgrid(256, 4);
    // init: reads parity 0 (zeros), writes parity 1, eps = eps_list[0]
    step_kernel<<<sgrid, 256>>>(0, 0, 1, 0.f, 0xF);
    // 20 scan steps with 0.5 averaging
    for (int t = 0; t < 20; t++) {
        int rp = 1 - (t & 1);
        int wp = t & 1;
        step_kernel<<<sgrid, 256>>>(t, rp, wp, 0.5f, 0xF);
    }
    // final extrapolation at eps = blur^2 (index 20), no averaging.
    // first f_ab, f_aa, g_bb (read parity 1 -> write parity 0)
    step_kernel<<<sgrid, 256>>>(20, 1, 0, 0.f, 0b1101);
    // then g_ab from the NEW f_ab (read parity 0 -> write parity 0)
    step_kernel<<<sgrid, 256>>>(20, 0, 0, 0.f, 0b0010);

    reduce_kernel<<<1, 256>>>(out);
}

// round 4
// speedup vs baseline: 1.0060x; 1.0001x over previous
#include <cuda_runtime.h>
#include <math.h>
#include <float.h>

#define ND 2048
#define NS 1024
#define DIN 768
#define DOUT 64

#define LOG2E 1.4426950408889634f
#define LN2   0.6931471805599453f
#define LOGA  (-7.6246189861593985f)   /* -ln(2048) */
#define LOGB  (-6.9314718055994531f)   /* -ln(1024) */
#define BLUR2 0.0025f

// ---- static device scratch (no cudaMalloc allowed) ----
__device__ float g_x[ND * DOUT];
__device__ float g_y[NS * DOUT];
__device__ float g_Cxy[ND * NS];
__device__ float g_Cyx[NS * ND];
__device__ float g_Cxx[ND * ND];
__device__ float g_Cyy[NS * NS];
__device__ float g_f_ab[2][ND];
__device__ float g_g_ab[2][NS];
__device__ float g_f_aa[2][ND];
__device__ float g_g_bb[2][NS];
__device__ float g_eps[21];

// ---------------------------------------------------------------------------
// zero the parity-0 potential buffers (read by the init step)
// ---------------------------------------------------------------------------
__global__ void zero_kernel() {
    int t = threadIdx.x + blockIdx.x * blockDim.x;
    if (t < ND) { g_f_ab[0][t] = 0.f; g_f_aa[0][t] = 0.f; }
    if (t < NS) { g_g_ab[0][t] = 0.f; g_g_bb[0][t] = 0.f; }
}

// ---------------------------------------------------------------------------
// projection: x = d @ M  (2048x768 * 768x64), y = s @ M (1024x768 * 768x64)
// 64-row tiles, K-tiles of 32, 4x4 register blocking per thread.
// ---------------------------------------------------------------------------
__global__ __launch_bounds__(256) void proj_kernel(const float* __restrict__ d,
                                                   const float* __restrict__ s,
                                                   const float* __restrict__ M) {
    __shared__ float ds[64][33];   // [row][k], padded
    __shared__ float Ms[32][64];   // [k][col]

    int b = blockIdx.x;
    const float* src;
    float* dst;
    int rowbase;
    if (b < 32) { src = d; dst = g_x; rowbase = b * 64; }
    else        { src = s; dst = g_y; rowbase = (b - 32) * 64; }

    int tid = threadIdx.x;
    int tr = tid >> 4, tc = tid & 15;
    float acc[4][4];
#pragma unroll
    for (int i = 0; i < 4; i++)
#pragma unroll
        for (int j = 0; j < 4; j++) acc[i][j] = 0.f;

    for (int kt = 0; kt < DIN; kt += 32) {
        __syncthreads();
        for (int i = tid; i < 64 * 32; i += 256) {
            int rr = i >> 5, kk = i & 31;
            ds[rr][kk] = src[(size_t)(rowbase + rr) * DIN + kt + kk];
        }
        for (int i = tid; i < 32 * 64; i += 256) {
            int kr = i >> 6, kc = i & 63;
            Ms[kr][kc] = M[(size_t)(kt + kr) * 64 + kc];
        }
        __syncthreads();
#pragma unroll
        for (int kk = 0; kk < 32; kk++) {
            float4 bv = *reinterpret_cast<const float4*>(&Ms[kk][tc * 4]);
#pragma unroll
            for (int i = 0; i < 4; i++) {
                float a = ds[tr * 4 + i][kk];
                acc[i][0] = fmaf(a, bv.x, acc[i][0]);
                acc[i][1] = fmaf(a, bv.y, acc[i][1]);
                acc[i][2] = fmaf(a, bv.z, acc[i][2]);
                acc[i][3] = fmaf(a, bv.w, acc[i][3]);
            }
        }
    }
#pragma unroll
    for (int i = 0; i < 4; i++) {
        float4 v = make_float4(acc[i][0], acc[i][1], acc[i][2], acc[i][3]);
        *reinterpret_cast<float4*>(&dst[(size_t)(rowbase + tr * 4 + i) * 64 + tc * 4]) = v;
    }
}

// ---------------------------------------------------------------------------
// diameter + eps schedule: per-dim min/max over union of x and y,
// diam^2 = sum (max-min)^2 ; eps_t = max(diam2 * 0.25^t, blur^2)
// ---------------------------------------------------------------------------
__global__ __launch_bounds__(512) void minmax_eps_kernel() {
    __shared__ float smn[512], smx[512];
    int tid = threadIdx.x;
    int dim = tid & 63;
    int grp = tid >> 6;   // 0..7
    float mn = FLT_MAX, mx = -FLT_MAX;
    for (int r = grp; r < ND; r += 8) {
        float v = g_x[r * 64 + dim];
        mn = fminf(mn, v); mx = fmaxf(mx, v);
    }
    for (int r = grp; r < NS; r += 8) {
        float v = g_y[r * 64 + dim];
        mn = fminf(mn, v); mx = fmaxf(mx, v);
    }
    smn[tid] = mn; smx[tid] = mx;
    __syncthreads();
    if (grp == 0) {
        for (int gq = 1; gq < 8; gq++) {
            mn = fminf(mn, smn[gq * 64 + dim]);
            mx = fmaxf(mx, smx[gq * 64 + dim]);
        }
        float dd = mx - mn;
        smn[dim] = dd * dd;
    }
    __syncthreads();
    if (tid == 0) {
        float diam2 = 0.f;
        for (int k = 0; k < 64; k++) diam2 += smn[k];
        float e = diam2;
        for (int t = 0; t < 20; t++) {
            g_eps[t] = fmaxf(e, BLUR2);
            e *= 0.25f;
        }
        g_eps[20] = BLUR2;
    }
}

// ---------------------------------------------------------------------------
// cost matrices: C[i][j] = 0.5*|a_i|^2 + 0.5*|b_j|^2 - a_i . b_j
// one kernel covers Cxy / Cyx / Cxx / Cyy via block index ranges.
// 64x64 output tiles, K = 64 (full), 4x4 register blocking.
// ---------------------------------------------------------------------------
__global__ __launch_bounds__(256) void cost_kernel() {
    int b = blockIdx.x;
    const float *A, *B;
    float* C;
    int NB, bi, bj;
    if (b < 512)       { A = g_x; B = g_y; C = g_Cxy; NB = NS; int i = b;        bi = i >> 4; bj = i & 15; }
    else if (b < 1024) { A = g_y; B = g_x; C = g_Cyx; NB = ND; int i = b - 512;  bi = i >> 5; bj = i & 31; }
    else if (b < 2048) { A = g_x; B = g_x; C = g_Cxx; NB = ND; int i = b - 1024; bi = i >> 5; bj = i & 31; }
    else               { A = g_y; B = g_y; C = g_Cyy; NB = NS; int i = b - 2048; bi = i >> 4; bj = i & 15; }

    __shared__ float As[64][65];    // [row][k]
    __shared__ float BsT[64][68];   // [k][col]
    __shared__ float an[64], bn[64];

    int tid = threadIdx.x;
    for (int i = tid; i < 64 * 16; i += 256) {
        int rr = i >> 4, kq = i & 15;
        float4 v = *reinterpret_cast<const float4*>(&A[(size_t)(bi * 64 + rr) * 64 + kq * 4]);
        As[rr][kq * 4 + 0] = v.x; As[rr][kq * 4 + 1] = v.y;
        As[rr][kq * 4 + 2] = v.z; As[rr][kq * 4 + 3] = v.w;
    }
    for (int i = tid; i < 64 * 16; i += 256) {
        int rr = i >> 4, kq = i & 15;
        float4 v = *reinterpret_cast<const float4*>(&B[(size_t)(bj * 64 + rr) * 64 + kq * 4]);
        BsT[kq * 4 + 0][rr] = v.x; BsT[kq * 4 + 1][rr] = v.y;
        BsT[kq * 4 + 2][rr] = v.z; BsT[kq * 4 + 3][rr] = v.w;
    }
    __syncthreads();
    if (tid < 64) {
        float sacc = 0.f;
#pragma unroll
        for (int k = 0; k < 64; k++) sacc = fmaf(As[tid][k], As[tid][k], sacc);
        an[tid] = 0.5f * sacc;
    } else if (tid < 128) {
        int c = tid - 64;
        float sacc = 0.f;
#pragma unroll
        for (int k = 0; k < 64; k++) sacc = fmaf(BsT[k][c], BsT[k][c], sacc);
        bn[c] = 0.5f * sacc;
    }
    __syncthreads();

    int tr = tid >> 4, tc = tid & 15;
    float acc[4][4];
#pragma unroll
    for (int i = 0; i < 4; i++)
#pragma unroll
        for (int j = 0; j < 4; j++) acc[i][j] = 0.f;

#pragma unroll
    for (int kk = 0; kk < 64; kk++) {
        float4 bv = *reinterpret_cast<const float4*>(&BsT[kk][tc * 4]);
#pragma unroll
        for (int i = 0; i < 4; i++) {
            float a = As[tr * 4 + i][kk];
            acc[i][0] = fmaf(a, bv.x, acc[i][0]);
            acc[i][1] = fmaf(a, bv.y, acc[i][1]);
            acc[i][2] = fmaf(a, bv.z, acc[i][2]);
            acc[i][3] = fmaf(a, bv.w, acc[i][3]);
        }
    }
#pragma unroll
    for (int i = 0; i < 4; i++) {
        int row = bi * 64 + tr * 4 + i;
        float4 o;
        o.x = an[tr * 4 + i] + bn[tc * 4 + 0] - acc[i][0];
        o.y = an[tr * 4 + i] + bn[tc * 4 + 1] - acc[i][1];
        o.z = an[tr * 4 + i] + bn[tc * 4 + 2] - acc[i][2];
        o.w = an[tr * 4 + i] + bn[tc * 4 + 3] - acc[i][3];
        *reinterpret_cast<float4*>(&C[(size_t)row * NB + bj * 64 + tc * 4]) = o;
    }
}

// ---------------------------------------------------------------------------
// one Sinkhorn sweep: 4 tasks (ft / gt / f_aa / g_bb), one warp per row.
// ft_i = -eps*(logw + ln2*LSE2_j((g_j - C_ij) * log2e/eps))
// out  = blend ? 0.5*(old + ft) : ft
// ---------------------------------------------------------------------------
__global__ __launch_bounds__(256) void step_kernel(int step, int rp, int wp,
                                                   float blend, int mask) {
    int task = blockIdx.y;
    if (!((mask >> task) & 1)) return;

    const float* C;
    const float* gv;
    const float* oldv;
    float* outv;
    int len, nrows;
    float logw;
    switch (task) {
        case 0: C = g_Cxy; len = NS; nrows = ND; gv = g_g_ab[rp]; oldv = g_f_ab[rp]; outv = g_f_ab[wp]; logw = LOGB; break;
        case 1: C = g_Cyx; len = ND; nrows = NS; gv = g_f_ab[rp]; oldv = g_g_ab[rp]; outv = g_g_ab[wp]; logw = LOGA; break;
        case 2: C = g_Cxx; len = ND; nrows = ND; gv = g_f_aa[rp]; oldv = g_f_aa[rp]; outv = g_f_aa[wp]; logw = LOGA; break;
        default:C = g_Cyy; len = NS; nrows = NS; gv = g_g_bb[rp]; oldv = g_g_bb[rp]; outv = g_g_bb[wp]; logw = LOGB; break;
    }

    float eps = g_eps[step];
    float ie = LOG2E / eps;

    __shared__ float gs[2048];
    int tid = threadIdx.x;
    for (int j = tid; j < len; j += 256) gs[j] = gv[j] * ie;
    __syncthreads();

    int wid = tid >> 5, lane = tid & 31;
    int row = blockIdx.x * 8 + wid;
    if (row >= nrows) return;

    const float* Crow = C + (size_t)row * len;
    float m = 0.f, ssum = 0.f;

    for (int base = 0; base < len; base += 1024) {
        float u[32];
#pragma unroll
        for (int k = 0; k < 32; k++) {
            int j = base + lane + (k << 5);
            u[k] = fmaf(Crow[j], -ie, gs[j]);
        }
        float mloc = u[0];
#pragma unroll
        for (int k = 1; k < 32; k++) mloc = fmaxf(mloc, u[k]);
        float sl = 0.f;
#pragma unroll
        for (int k = 0; k < 32; k++) sl += exp2f(u[k] - mloc);
        if (base == 0) {
            m = mloc; ssum = sl;
        } else {
            float Mx = fmaxf(m, mloc);
            ssum = ssum * exp2f(m - Mx) + sl * exp2f(mloc - Mx);
            m = Mx;
        }
    }
#pragma unroll
    for (int off = 16; off > 0; off >>= 1) {
        float m2 = __shfl_xor_sync(0xffffffffu, m, off);
        float s2 = __shfl_xor_sync(0xffffffffu, ssum, off);
        float Mx = fmaxf(m, m2);
        ssum = ssum * exp2f(m - Mx) + s2 * exp2f(m2 - Mx);
        m = Mx;
    }
    if (lane == 0) {
        float ft = -eps * (logw + LN2 * (m + __log2f(ssum)));
        outv[row] = (blend != 0.f) ? 0.5f * (oldv[row] + ft) : ft;
    }
}

// ---------------------------------------------------------------------------
// final scalar: loss = mean(f_ab - f_aa) + mean(g_ab - g_bb); out = exp(-loss)
// ---------------------------------------------------------------------------
__global__ __launch_bounds__(256) void reduce_kernel(float* out) {
    __shared__ double sh[256];
    int tid = threadIdx.x;
    double a1 = 0.0, a2 = 0.0;
    for (int i = tid; i < ND; i += 256)
        a1 += (double)g_f_ab[0][i] - (double)g_f_aa[0][i];
    for (int i = tid; i < NS; i += 256)
        a2 += (double)g_g_ab[0][i] - (double)g_g_bb[0][i];
    sh[tid] = a1 / (double)ND + a2 / (double)NS;
    __syncthreads();
    for (int off = 128; off > 0; off >>= 1) {
        if (tid < off) sh[tid] += sh[tid + off];
        __syncthreads();
    }
    if (tid == 0) out[0] = expf((float)(-sh[0]));
}

// ---------------------------------------------------------------------------
extern "C" void kernel_launch(void* const* d_in, const int* in_sizes, int n_in,
                              void* d_out, int out_size) {
    const float* d = (const float*)d_in[0];   // [2048, 768]
    const float* s = (const float*)d_in[1];   // [1024, 768]
    const float* M = (const float*)d_in[2];   // [768, 64]
    float* out = (float*)d_out;

    zero_kernel<<<2, 1024>>>();
    proj_kernel<<<48, 256>>>(d, s, M);
    minmax_eps_kernel<<<1, 512>>>();
    cost_kernel<<<2304, 256>>>();

    dim3 sgrid(256, 4);
    // init: reads parity 0 (zeros), writes parity 1, eps = eps_list[0]
    step_kernel<<<sgrid, 256>>>(0, 0, 1, 0.f, 0xF);
    // 20 scan steps with 0.5 averaging
    for (int t = 0; t < 20; t++) {
        int rp = 1 - (t & 1);
        int wp = t & 1;
        step_kernel<<<sgrid, 256>>>(t, rp, wp, 0.5f, 0xF);
    }
    // final extrapolation at eps = blur^2 (index 20), no averaging.
    // first f_ab, f_aa, g_bb (read parity 1 -> write parity 0)
    step_kernel<<<sgrid, 256>>>(20, 1, 0, 0.f, 0b1101);
    // then g_ab from the NEW f_ab (read parity 0 -> write parity 0)
    step_kernel<<<sgrid, 256>>>(20, 0, 0, 0.f, 0b0010);

    reduce_kernel<<<1, 256>>>(out);
}